// round 15
// baseline (speedup 1.0000x reference)
#include <cuda_runtime.h>
#include <math.h>
#include <cstdint>

#define B_SZ   4
#define S_LEN  2048
#define D_DIM  1024
#define NH     16
#define HD_    64
#define QKV_LD 3072

// Scratch (no runtime allocation allowed). All tf32-bit buffers are uint32.
__device__ uint32_t g_xa[(size_t)B_SZ * S_LEN * D_DIM];   // x  (tf32)
__device__ uint32_t g_wa[(size_t)QKV_LD * D_DIM];         // w_attn (tf32)
__device__ uint32_t g_wp[(size_t)D_DIM * D_DIM];          // w_proj (tf32)
__device__ uint32_t g_qkv[(size_t)B_SZ * S_LEN * QKV_LD]; // qkv (tf32)
__device__ uint32_t g_att[(size_t)B_SZ * S_LEN * D_DIM];  // attn out (tf32)

// ---------------------------------------------------------------------------
// helpers (target-neutral; plain sm_103)
// ---------------------------------------------------------------------------
__device__ __forceinline__ uint32_t cvt_tf32(float f) {
    uint32_t r;
    asm("cvt.rna.tf32.f32 %0, %1;" : "=r"(r) : "f"(f));
    return r;
}

__device__ __forceinline__ uint32_t smem_u32(const void* p) {
    uint32_t a;
    asm("{ .reg .u64 t; cvta.to.shared.u64 t, %1; cvt.u32.u64 %0, t; }"
        : "=r"(a) : "l"(p));
    return a;
}

#define CP_ASYNC16(dst_u32, src_ptr)                                          \
    asm volatile("cp.async.cg.shared.global [%0], [%1], 16;"                  \
                 :: "r"(dst_u32), "l"(src_ptr))
#define CP_COMMIT() asm volatile("cp.async.commit_group;" ::: "memory")
#define CP_WAIT(n)  asm volatile("cp.async.wait_group %0;" :: "n"(n) : "memory")

#define MMA_TF32(d0, d1, d2, d3, a0, a1, a2, a3, b0, b1)                      \
    asm volatile(                                                             \
        "mma.sync.aligned.m16n8k8.row.col.f32.tf32.tf32.f32 "                 \
        "{%0,%1,%2,%3}, {%4,%5,%6,%7}, {%8,%9}, {%0,%1,%2,%3};"               \
        : "+f"(d0), "+f"(d1), "+f"(d2), "+f"(d3)                              \
        : "r"(a0), "r"(a1), "r"(a2), "r"(a3), "r"(b0), "r"(b1))

// ldmatrix x4: lanes 0-7 supply row addresses of matrix 0, 8-15 matrix 1, etc.
#define LDSM_X4(r0, r1, r2, r3, addr)                                         \
    asm volatile("ldmatrix.sync.aligned.m8n8.x4.shared.b16 {%0,%1,%2,%3}, [%4];" \
                 : "=r"(r0), "=r"(r1), "=r"(r2), "=r"(r3) : "r"(addr))

// ---------------------------------------------------------------------------
// One-shot tf32 conversion of x, w_attn, w_proj (bandwidth-bound, ~13us).
// ---------------------------------------------------------------------------
#define NX4  (B_SZ * S_LEN * D_DIM / 4)
#define NWA4 (QKV_LD * D_DIM / 4)
#define NWP4 (D_DIM * D_DIM / 4)
#define NCVT4 (NX4 + NWA4 + NWP4)

__global__ __launch_bounds__(256)
void cvt_inputs(const float4* __restrict__ x, const float4* __restrict__ wa,
                const float4* __restrict__ wp) {
    const int i = blockIdx.x * 256 + threadIdx.x;
    float4 v;
    uint4* dst;
    if (i < NX4)            { v = x[i];               dst = (uint4*)g_xa + i; }
    else if (i < NX4 + NWA4){ v = wa[i - NX4];        dst = (uint4*)g_wa + (i - NX4); }
    else                    { v = wp[i - NX4 - NWA4]; dst = (uint4*)g_wp + (i - NX4 - NWA4); }
    uint4 o;
    o.x = cvt_tf32(v.x); o.y = cvt_tf32(v.y);
    o.z = cvt_tf32(v.z); o.w = cvt_tf32(v.w);
    *dst = o;
}

// ---------------------------------------------------------------------------
// Tensor-core GEMM (tf32 mma.sync, NT): C[M,N] = A[M,K] * B[N,K]^T.
// (Round-10 version, unchanged: 2 CTAs/SM, 128x128 tile, 3-stage cp.async,
// ldmatrix fragments.)
// ---------------------------------------------------------------------------
#define SROW 36
#define ASTG (128 * SROW)
#define STG_BYTES (2 * ASTG * 4)               // A+B per stage = 36864
#define GSMEM_BYTES (3 * STG_BYTES)            // 110592

template <bool OUT_TF32>
__global__ __launch_bounds__(256, 2)
void sgemm_tc(const uint32_t* __restrict__ A, const uint32_t* __restrict__ B,
              void* __restrict__ Cv, int M, int N, int K) {
    extern __shared__ __align__(16) uint32_t sm[];
    const uint32_t sbase = smem_u32(sm);

    const int tid  = threadIdx.x;
    const int wid  = tid >> 5;
    const int lane = tid & 31;
    const int g    = lane >> 2;
    const int t    = lane & 3;
    const int j8   = lane >> 3;
    const int r8   = lane & 7;
    const int row0 = blockIdx.y << 7;
    const int col0 = blockIdx.x << 7;
    const int warp_m = (wid & 1) * 64;
    const int warp_n = (wid >> 1) * 32;

    const int rbase = tid >> 3;
    const int c4    = (tid & 7) * 4;

    const uint32_t* Abase = A + (size_t)(row0 + rbase) * K + c4;
    const uint32_t* Bbase = B + (size_t)(col0 + rbase) * K + c4;
    const uint32_t adst = sbase + (uint32_t)(rbase * SROW + c4) * 4;
    const uint32_t bdst = sbase + (uint32_t)(ASTG + rbase * SROW + c4) * 4;

    const uint32_t aldm = sbase +
        (uint32_t)((warp_m + (j8 & 1) * 8 + r8) * SROW + (j8 >> 1) * 4) * 4;
    const uint32_t bldm = sbase +
        (uint32_t)(ASTG + (warp_n + (j8 >> 1) * 8 + r8) * SROW + (j8 & 1) * 4) * 4;

    const int KT = K >> 5;

    float acc[4][4][4];
#pragma unroll
    for (int i = 0; i < 4; i++)
#pragma unroll
        for (int j = 0; j < 4; j++)
#pragma unroll
            for (int k = 0; k < 4; k++) acc[i][j][k] = 0.f;

#pragma unroll
    for (int s = 0; s < 2; s++) {
        const int kb = s << 5;
        const uint32_t so = (uint32_t)s * STG_BYTES;
#pragma unroll
        for (int i = 0; i < 4; i++) {
            CP_ASYNC16(adst + so + i * (32 * SROW * 4), Abase + (size_t)(32 * i) * K + kb);
            CP_ASYNC16(bdst + so + i * (32 * SROW * 4), Bbase + (size_t)(32 * i) * K + kb);
        }
        CP_COMMIT();
    }

    uint32_t so = 0;
    int so_next = STG_BYTES;

    for (int kt = 0; kt < KT; kt++) {
        CP_WAIT(1);
        __syncthreads();

        if (kt + 2 < KT) {
            const int kb = (kt + 2) << 5;
            const uint32_t po = (uint32_t)(((kt + 2) % 3)) * STG_BYTES;
#pragma unroll
            for (int i = 0; i < 4; i++) {
                CP_ASYNC16(adst + po + i * (32 * SROW * 4), Abase + (size_t)(32 * i) * K + kb);
                CP_ASYNC16(bdst + po + i * (32 * SROW * 4), Bbase + (size_t)(32 * i) * K + kb);
            }
        }
        CP_COMMIT();

#pragma unroll
        for (int ks = 0; ks < 4; ks++) {
            uint32_t af[4][4], bf[4][2];
#pragma unroll
            for (int mt = 0; mt < 4; mt++)
                LDSM_X4(af[mt][0], af[mt][1], af[mt][2], af[mt][3],
                        aldm + so + (uint32_t)(mt * 16 * SROW + ks * 8) * 4);
#pragma unroll
            for (int p = 0; p < 2; p++)
                LDSM_X4(bf[2 * p][0], bf[2 * p][1], bf[2 * p + 1][0], bf[2 * p + 1][1],
                        bldm + so + (uint32_t)(p * 16 * SROW + ks * 8) * 4);
#pragma unroll
            for (int mt = 0; mt < 4; mt++)
#pragma unroll
                for (int nt = 0; nt < 4; nt++)
                    MMA_TF32(acc[mt][nt][0], acc[mt][nt][1],
                             acc[mt][nt][2], acc[mt][nt][3],
                             af[mt][0], af[mt][1], af[mt][2], af[mt][3],
                             bf[nt][0], bf[nt][1]);
        }

        so = (uint32_t)so_next;
        so_next += STG_BYTES;
        if (so_next == 3 * STG_BYTES) so_next = 0;
    }

#pragma unroll
    for (int mt = 0; mt < 4; mt++) {
        const int r_lo = row0 + warp_m + mt * 16 + g;
#pragma unroll
        for (int nt = 0; nt < 4; nt++) {
            const int cc = col0 + warp_n + nt * 8 + 2 * t;
            if (OUT_TF32) {
                uint32_t* C = (uint32_t*)Cv;
                *(uint2*)(C + (size_t)r_lo * N + cc) =
                    make_uint2(cvt_tf32(acc[mt][nt][0]), cvt_tf32(acc[mt][nt][1]));
                *(uint2*)(C + (size_t)(r_lo + 8) * N + cc) =
                    make_uint2(cvt_tf32(acc[mt][nt][2]), cvt_tf32(acc[mt][nt][3]));
            } else {
                float* C = (float*)Cv;
                *(float2*)(C + (size_t)r_lo * N + cc) =
                    make_float2(acc[mt][nt][0], acc[mt][nt][1]);
                *(float2*)(C + (size_t)(r_lo + 8) * N + cc) =
                    make_float2(acc[mt][nt][2], acc[mt][nt][3]);
            }
        }
    }
}

// ---------------------------------------------------------------------------
// Causal flash attention, tf32 mma.sync. Round-13 structure (BQ=128,
// 256 threads, 2 CTAs/SM via reg cap, 2-stage cp.async, ldmatrix K/Q/P).
// Round-15 micro-opts (both bit-exact):
//  - Q pre-scaled by 0.125 at staging (power of two -> exact; removes the
//    32 FMULs/tile/warp from the serial softmax phase).
//  - V row stride 68 -> 72: PV scalar-LDS bank index becomes (8t+g)%32,
//    a perfect warp permutation -> conflict-free (was 2-way at stride 68).
// Smem: 2 stages x (K 64x68 | V 64x72) + Q/P 128x68 = 106496 B; 2 CTAs/SM.
// ---------------------------------------------------------------------------
#define ATT_SROW 68
#define ATT_VROW 72
#define ATT_KSZ  (64 * ATT_SROW)                  // 4352 u32
#define ATT_STG  (ATT_KSZ + 64 * ATT_VROW)        // 8960 u32 per stage
#define ATT_PS   (2 * ATT_STG)                    // 17920 u32
#define ATT_SMEM_BYTES ((ATT_PS + 128 * ATT_SROW) * 4)   // 106496

__global__ __launch_bounds__(256, 2)
void attn_mma(const uint32_t* __restrict__ qkv, uint32_t* __restrict__ out) {
    extern __shared__ __align__(16) uint32_t sm2[];
    const uint32_t s2base = smem_u32(sm2);

    const int bh = blockIdx.y;
    const int b  = bh >> 4;
    const int h  = bh & 15;
    const int q0 = (int)(gridDim.x - 1 - blockIdx.x) << 7;

    const int tid  = threadIdx.x;
    const int wid  = tid >> 5;
    const int lane = tid & 31;
    const int g    = lane >> 2;
    const int t    = lane & 3;
    const int j8   = lane >> 3;
    const int r8   = lane & 7;

    const size_t row_base = (size_t)b * S_LEN;

    const int lr  = tid >> 2;
    const int lcb = (tid & 3) * 16;
    const uint32_t kdst0 = s2base + (uint32_t)(lr * ATT_SROW + lcb) * 4;
    const uint32_t vdst0 = s2base + (uint32_t)(ATT_KSZ + lr * ATT_VROW + lcb) * 4;
    const uint32_t* kgbase = qkv + (row_base + lr) * QKV_LD + D_DIM + h * HD_ + lcb;

    const uint32_t kldm = s2base +
        (uint32_t)(((j8 >> 1) * 8 + r8) * ATT_SROW + (j8 & 1) * 4) * 4;
    const uint32_t pldm = s2base +
        (uint32_t)(ATT_PS + (wid * 16 + (j8 & 1) * 8 + r8) * ATT_SROW + (j8 >> 1) * 4) * 4;

    const int nkt = (q0 >> 6) + 2;

    {
#pragma unroll
        for (int i = 0; i < 4; i++) {
            CP_ASYNC16(kdst0 + i * 16, kgbase + i * 4);
            CP_ASYNC16(vdst0 + i * 16, kgbase + D_DIM + i * 4);
        }
        CP_COMMIT();
    }

    // ---- stage Q tile, pre-scaled by 0.125 (exact: exponent-only) ----
#pragma unroll
    for (int i = 0; i < 8; i++) {
        const int idx = tid + i * 256;
        const int r   = idx >> 4;
        const int c4  = (idx & 15) * 4;
        uint4 v = *(const uint4*)(qkv + (row_base + q0 + r) * QKV_LD + h * HD_ + c4);
        uint32_t* p = sm2 + ATT_PS + r * ATT_SROW + c4;
        p[0] = __float_as_uint(__uint_as_float(v.x) * 0.125f);
        p[1] = __float_as_uint(__uint_as_float(v.y) * 0.125f);
        p[2] = __float_as_uint(__uint_as_float(v.z) * 0.125f);
        p[3] = __float_as_uint(__uint_as_float(v.w) * 0.125f);
    }
    __syncthreads();

    uint32_t qf[8][4];
#pragma unroll
    for (int ks = 0; ks < 8; ks++)
        LDSM_X4(qf[ks][0], qf[ks][1], qf[ks][2], qf[ks][3],
                pldm + (uint32_t)(ks * 8) * 4);

    float m0 = -1e30f, m1 = -1e30f, l0 = 0.f, l1 = 0.f;
    float o[8][4];
#pragma unroll
    for (int nt = 0; nt < 8; nt++)
#pragma unroll
        for (int j = 0; j < 4; j++) o[nt][j] = 0.f;

    uint32_t* const pw = sm2 + ATT_PS + wid * (16 * ATT_SROW);
    const int myrowmax = q0 + wid * 16 + 15;
    const unsigned FULL = 0xffffffffu;

    for (int kt = 0; kt < nkt; kt++) {
        const int k0 = kt << 6;

        CP_WAIT(0);
        __syncthreads();

        if (kt + 1 < nkt) {
            const uint32_t so = (uint32_t)(((kt + 1) & 1) * ATT_STG) * 4;
            const uint32_t* kg = kgbase + (size_t)((kt + 1) << 6) * QKV_LD;
#pragma unroll
            for (int i = 0; i < 4; i++) {
                CP_ASYNC16(kdst0 + so + i * 16, kg + i * 4);
                CP_ASYNC16(vdst0 + so + i * 16, kg + D_DIM + i * 4);
            }
            CP_COMMIT();
        }

        const uint32_t kso = (uint32_t)((kt & 1) * ATT_STG) * 4;
        const uint32_t* Vsb = sm2 + (size_t)(kt & 1) * ATT_STG + ATT_KSZ;

        if (k0 <= myrowmax) {
            float acc[8][4];
#pragma unroll
            for (int nt = 0; nt < 8; nt++)
#pragma unroll
                for (int j = 0; j < 4; j++) acc[nt][j] = 0.f;

#pragma unroll
            for (int ks = 0; ks < 8; ks++) {
                uint32_t bf[8][2];
#pragma unroll
                for (int p = 0; p < 4; p++)
                    LDSM_X4(bf[2 * p][0], bf[2 * p][1], bf[2 * p + 1][0], bf[2 * p + 1][1],
                            kldm + kso + (uint32_t)(p * 16 * ATT_SROW + ks * 8) * 4);
#pragma unroll
                for (int nt = 0; nt < 8; nt++)
                    MMA_TF32(acc[nt][0], acc[nt][1], acc[nt][2], acc[nt][3],
                             qf[ks][0], qf[ks][1], qf[ks][2], qf[ks][3],
                             bf[nt][0], bf[nt][1]);
            }

            // ---- causal mask (scores already scaled via Q) ----
            const int r0 = q0 + wid * 16 + g;
            const int r1 = r0 + 8;
            if (k0 + 63 > q0 + wid * 16) {
#pragma unroll
                for (int nt = 0; nt < 8; nt++) {
                    const int col = k0 + nt * 8 + 2 * t;
                    if (col > r0)     acc[nt][0] = -1e30f;
                    if (col + 1 > r0) acc[nt][1] = -1e30f;
                    if (col > r1)     acc[nt][2] = -1e30f;
                    if (col + 1 > r1) acc[nt][3] = -1e30f;
                }
            }

            float mt0 = -1e30f, mt1 = -1e30f;
#pragma unroll
            for (int nt = 0; nt < 8; nt++) {
                mt0 = fmaxf(mt0, fmaxf(acc[nt][0], acc[nt][1]));
                mt1 = fmaxf(mt1, fmaxf(acc[nt][2], acc[nt][3]));
            }
            mt0 = fmaxf(mt0, __shfl_xor_sync(FULL, mt0, 1));
            mt0 = fmaxf(mt0, __shfl_xor_sync(FULL, mt0, 2));
            mt1 = fmaxf(mt1, __shfl_xor_sync(FULL, mt1, 1));
            mt1 = fmaxf(mt1, __shfl_xor_sync(FULL, mt1, 2));

            const float mn0 = fmaxf(m0, mt0);
            const float mn1 = fmaxf(m1, mt1);
            const float c0 = __expf(m0 - mn0);
            const float c1 = __expf(m1 - mn1);
            float s0 = 0.f, s1 = 0.f;
#pragma unroll
            for (int nt = 0; nt < 8; nt++) {
                acc[nt][0] = __expf(acc[nt][0] - mn0); s0 += acc[nt][0];
                acc[nt][1] = __expf(acc[nt][1] - mn0); s0 += acc[nt][1];
                acc[nt][2] = __expf(acc[nt][2] - mn1); s1 += acc[nt][2];
                acc[nt][3] = __expf(acc[nt][3] - mn1); s1 += acc[nt][3];
            }
            s0 += __shfl_xor_sync(FULL, s0, 1);
            s0 += __shfl_xor_sync(FULL, s0, 2);
            s1 += __shfl_xor_sync(FULL, s1, 1);
            s1 += __shfl_xor_sync(FULL, s1, 2);
            l0 = l0 * c0 + s0; m0 = mn0;
            l1 = l1 * c1 + s1; m1 = mn1;
#pragma unroll
            for (int nt = 0; nt < 8; nt++) {
                o[nt][0] *= c0; o[nt][1] *= c0;
                o[nt][2] *= c1; o[nt][3] *= c1;
            }

#pragma unroll
            for (int nt = 0; nt < 8; nt++) {
                uint32_t* p0 = pw + g * ATT_SROW + nt * 8 + 2 * t;
                uint32_t* p1 = pw + (g + 8) * ATT_SROW + nt * 8 + 2 * t;
                p0[0] = cvt_tf32(acc[nt][0]); p0[1] = cvt_tf32(acc[nt][1]);
                p1[0] = cvt_tf32(acc[nt][2]); p1[1] = cvt_tf32(acc[nt][3]);
            }
            __syncwarp();

#pragma unroll
            for (int ks = 0; ks < 8; ks++) {
                uint32_t pa[4];
                LDSM_X4(pa[0], pa[1], pa[2], pa[3], pldm + (uint32_t)(ks * 8) * 4);
#pragma unroll
                for (int nt = 0; nt < 8; nt++) {
                    const uint32_t* vb = Vsb + (ks * 8 + t) * ATT_VROW + nt * 8 + g;
                    const uint32_t b0 = vb[0];
                    const uint32_t b1 = vb[4 * ATT_VROW];
                    MMA_TF32(o[nt][0], o[nt][1], o[nt][2], o[nt][3],
                             pa[0], pa[1], pa[2], pa[3], b0, b1);
                }
            }
        }
    }

    const float i0 = 1.0f / l0;
    const float i1 = 1.0f / l1;
    const size_t r0 = row_base + q0 + wid * 16 + g;
#pragma unroll
    for (int nt = 0; nt < 8; nt++) {
        const int col = h * HD_ + nt * 8 + 2 * t;
        *(uint2*)(out + r0 * D_DIM + col) =
            make_uint2(cvt_tf32(o[nt][0] * i0), cvt_tf32(o[nt][1] * i0));
        *(uint2*)(out + (r0 + 8) * D_DIM + col) =
            make_uint2(cvt_tf32(o[nt][2] * i1), cvt_tf32(o[nt][3] * i1));
    }
}

// ---------------------------------------------------------------------------
extern "C" void kernel_launch(void* const* d_in, const int* in_sizes, int n_in,
                              void* d_out, int out_size) {
    const float* x      = (const float*)d_in[0];  // [B, S, D]
    const float* w_attn = (const float*)d_in[1];  // [3D, D]
    const float* w_proj = (const float*)d_in[2];  // [D, D]
    float* outp         = (float*)d_out;          // [B, S, D]

    void *p_xa, *p_wa, *p_wp, *p_qkv, *p_att;
    cudaGetSymbolAddress(&p_xa, g_xa);
    cudaGetSymbolAddress(&p_wa, g_wa);
    cudaGetSymbolAddress(&p_wp, g_wp);
    cudaGetSymbolAddress(&p_qkv, g_qkv);
    cudaGetSymbolAddress(&p_att, g_att);

    const int M = B_SZ * S_LEN;  // 8192

    cudaFuncSetAttribute(sgemm_tc<true>,
                         cudaFuncAttributeMaxDynamicSharedMemorySize, GSMEM_BYTES);
    cudaFuncSetAttribute(sgemm_tc<false>,
                         cudaFuncAttributeMaxDynamicSharedMemorySize, GSMEM_BYTES);
    cudaFuncSetAttribute(attn_mma,
                         cudaFuncAttributeMaxDynamicSharedMemorySize, ATT_SMEM_BYTES);

    // 0) one-shot tf32 conversion of inputs
    cvt_inputs<<<NCVT4 / 256, 256>>>((const float4*)x, (const float4*)w_attn,
                                     (const float4*)w_proj);

    // 1) QKV = X @ W_attn^T  -> tf32 bits   (128x128 tiles, 2 CTAs/SM)
    sgemm_tc<true><<<dim3(QKV_LD / 128, M / 128), 256, GSMEM_BYTES>>>(
        (const uint32_t*)p_xa, (const uint32_t*)p_wa, p_qkv, M, QKV_LD, D_DIM);

    // 2) causal attention -> att (tf32 bits)  (BQ=128, 2 CTAs/SM)
    attn_mma<<<dim3(S_LEN / 128, B_SZ * NH), 256, ATT_SMEM_BYTES>>>(
        (const uint32_t*)p_qkv, (uint32_t*)p_att);

    // 3) out = att @ W_proj^T  -> fp32      (128x128 tiles, 2 CTAs/SM)
    sgemm_tc<false><<<dim3(D_DIM / 128, M / 128), 256, GSMEM_BYTES>>>(
        (const uint32_t*)p_att, (const uint32_t*)p_wp, outp, M, D_DIM, D_DIM);
}

// round 16
// speedup vs baseline: 1.4043x; 1.4043x over previous
#include <cuda_runtime.h>
#include <math.h>
#include <cstdint>

#define B_SZ   4
#define S_LEN  2048
#define D_DIM  1024
#define NH     16
#define HD_    64
#define QKV_LD 3072

// Scratch (no runtime allocation allowed). All tf32-bit buffers are uint32.
__device__ uint32_t g_xa[(size_t)B_SZ * S_LEN * D_DIM];   // x  (tf32)
__device__ uint32_t g_wa[(size_t)QKV_LD * D_DIM];         // w_attn (tf32)
__device__ uint32_t g_wp[(size_t)D_DIM * D_DIM];          // w_proj (tf32)
__device__ uint32_t g_qkv[(size_t)B_SZ * S_LEN * QKV_LD]; // qkv (tf32)
__device__ uint32_t g_att[(size_t)B_SZ * S_LEN * D_DIM];  // attn out (tf32)

// ---------------------------------------------------------------------------
// helpers (target-neutral; plain sm_103)
// ---------------------------------------------------------------------------
__device__ __forceinline__ uint32_t cvt_tf32(float f) {
    uint32_t r;
    asm("cvt.rna.tf32.f32 %0, %1;" : "=r"(r) : "f"(f));
    return r;
}

__device__ __forceinline__ uint32_t smem_u32(const void* p) {
    uint32_t a;
    asm("{ .reg .u64 t; cvta.to.shared.u64 t, %1; cvt.u32.u64 %0, t; }"
        : "=r"(a) : "l"(p));
    return a;
}

#define CP_ASYNC16(dst_u32, src_ptr)                                          \
    asm volatile("cp.async.cg.shared.global [%0], [%1], 16;"                  \
                 :: "r"(dst_u32), "l"(src_ptr))
#define CP_COMMIT() asm volatile("cp.async.commit_group;" ::: "memory")
#define CP_WAIT(n)  asm volatile("cp.async.wait_group %0;" :: "n"(n) : "memory")

#define MMA_TF32(d0, d1, d2, d3, a0, a1, a2, a3, b0, b1)                      \
    asm volatile(                                                             \
        "mma.sync.aligned.m16n8k8.row.col.f32.tf32.tf32.f32 "                 \
        "{%0,%1,%2,%3}, {%4,%5,%6,%7}, {%8,%9}, {%0,%1,%2,%3};"               \
        : "+f"(d0), "+f"(d1), "+f"(d2), "+f"(d3)                              \
        : "r"(a0), "r"(a1), "r"(a2), "r"(a3), "r"(b0), "r"(b1))

// ldmatrix x4: lanes 0-7 supply row addresses of matrix 0, 8-15 matrix 1, etc.
#define LDSM_X4(r0, r1, r2, r3, addr)                                         \
    asm volatile("ldmatrix.sync.aligned.m8n8.x4.shared.b16 {%0,%1,%2,%3}, [%4];" \
                 : "=r"(r0), "=r"(r1), "=r"(r2), "=r"(r3) : "r"(addr))

// ---------------------------------------------------------------------------
// One-shot tf32 conversion of x, w_attn, w_proj (bandwidth-bound, ~13us).
// ---------------------------------------------------------------------------
#define NX4  (B_SZ * S_LEN * D_DIM / 4)
#define NWA4 (QKV_LD * D_DIM / 4)
#define NWP4 (D_DIM * D_DIM / 4)
#define NCVT4 (NX4 + NWA4 + NWP4)

__global__ __launch_bounds__(256)
void cvt_inputs(const float4* __restrict__ x, const float4* __restrict__ wa,
                const float4* __restrict__ wp) {
    const int i = blockIdx.x * 256 + threadIdx.x;
    float4 v;
    uint4* dst;
    if (i < NX4)            { v = x[i];               dst = (uint4*)g_xa + i; }
    else if (i < NX4 + NWA4){ v = wa[i - NX4];        dst = (uint4*)g_wa + (i - NX4); }
    else                    { v = wp[i - NX4 - NWA4]; dst = (uint4*)g_wp + (i - NX4 - NWA4); }
    uint4 o;
    o.x = cvt_tf32(v.x); o.y = cvt_tf32(v.y);
    o.z = cvt_tf32(v.z); o.w = cvt_tf32(v.w);
    *dst = o;
}

// ---------------------------------------------------------------------------
// Tensor-core GEMM (tf32 mma.sync, NT): C[M,N] = A[M,K] * B[N,K]^T.
// (Round-10 version, unchanged: 2 CTAs/SM, 128x128 tile, 3-stage cp.async,
// ldmatrix fragments.)
// ---------------------------------------------------------------------------
#define SROW 36
#define ASTG (128 * SROW)
#define STG_BYTES (2 * ASTG * 4)               // A+B per stage = 36864
#define GSMEM_BYTES (3 * STG_BYTES)            // 110592

template <bool OUT_TF32>
__global__ __launch_bounds__(256, 2)
void sgemm_tc(const uint32_t* __restrict__ A, const uint32_t* __restrict__ B,
              void* __restrict__ Cv, int M, int N, int K) {
    extern __shared__ __align__(16) uint32_t sm[];
    const uint32_t sbase = smem_u32(sm);

    const int tid  = threadIdx.x;
    const int wid  = tid >> 5;
    const int lane = tid & 31;
    const int g    = lane >> 2;
    const int t    = lane & 3;
    const int j8   = lane >> 3;
    const int r8   = lane & 7;
    const int row0 = blockIdx.y << 7;
    const int col0 = blockIdx.x << 7;
    const int warp_m = (wid & 1) * 64;
    const int warp_n = (wid >> 1) * 32;

    const int rbase = tid >> 3;
    const int c4    = (tid & 7) * 4;

    const uint32_t* Abase = A + (size_t)(row0 + rbase) * K + c4;
    const uint32_t* Bbase = B + (size_t)(col0 + rbase) * K + c4;
    const uint32_t adst = sbase + (uint32_t)(rbase * SROW + c4) * 4;
    const uint32_t bdst = sbase + (uint32_t)(ASTG + rbase * SROW + c4) * 4;

    const uint32_t aldm = sbase +
        (uint32_t)((warp_m + (j8 & 1) * 8 + r8) * SROW + (j8 >> 1) * 4) * 4;
    const uint32_t bldm = sbase +
        (uint32_t)(ASTG + (warp_n + (j8 >> 1) * 8 + r8) * SROW + (j8 & 1) * 4) * 4;

    const int KT = K >> 5;

    float acc[4][4][4];
#pragma unroll
    for (int i = 0; i < 4; i++)
#pragma unroll
        for (int j = 0; j < 4; j++)
#pragma unroll
            for (int k = 0; k < 4; k++) acc[i][j][k] = 0.f;

#pragma unroll
    for (int s = 0; s < 2; s++) {
        const int kb = s << 5;
        const uint32_t so = (uint32_t)s * STG_BYTES;
#pragma unroll
        for (int i = 0; i < 4; i++) {
            CP_ASYNC16(adst + so + i * (32 * SROW * 4), Abase + (size_t)(32 * i) * K + kb);
            CP_ASYNC16(bdst + so + i * (32 * SROW * 4), Bbase + (size_t)(32 * i) * K + kb);
        }
        CP_COMMIT();
    }

    uint32_t so = 0;
    int so_next = STG_BYTES;

    for (int kt = 0; kt < KT; kt++) {
        CP_WAIT(1);
        __syncthreads();

        if (kt + 2 < KT) {
            const int kb = (kt + 2) << 5;
            const uint32_t po = (uint32_t)(((kt + 2) % 3)) * STG_BYTES;
#pragma unroll
            for (int i = 0; i < 4; i++) {
                CP_ASYNC16(adst + po + i * (32 * SROW * 4), Abase + (size_t)(32 * i) * K + kb);
                CP_ASYNC16(bdst + po + i * (32 * SROW * 4), Bbase + (size_t)(32 * i) * K + kb);
            }
        }
        CP_COMMIT();

#pragma unroll
        for (int ks = 0; ks < 4; ks++) {
            uint32_t af[4][4], bf[4][2];
#pragma unroll
            for (int mt = 0; mt < 4; mt++)
                LDSM_X4(af[mt][0], af[mt][1], af[mt][2], af[mt][3],
                        aldm + so + (uint32_t)(mt * 16 * SROW + ks * 8) * 4);
#pragma unroll
            for (int p = 0; p < 2; p++)
                LDSM_X4(bf[2 * p][0], bf[2 * p][1], bf[2 * p + 1][0], bf[2 * p + 1][1],
                        bldm + so + (uint32_t)(p * 16 * SROW + ks * 8) * 4);
#pragma unroll
            for (int mt = 0; mt < 4; mt++)
#pragma unroll
                for (int nt = 0; nt < 4; nt++)
                    MMA_TF32(acc[mt][nt][0], acc[mt][nt][1],
                             acc[mt][nt][2], acc[mt][nt][3],
                             af[mt][0], af[mt][1], af[mt][2], af[mt][3],
                             bf[nt][0], bf[nt][1]);
        }

        so = (uint32_t)so_next;
        so_next += STG_BYTES;
        if (so_next == 3 * STG_BYTES) so_next = 0;
    }

#pragma unroll
    for (int mt = 0; mt < 4; mt++) {
        const int r_lo = row0 + warp_m + mt * 16 + g;
#pragma unroll
        for (int nt = 0; nt < 4; nt++) {
            const int cc = col0 + warp_n + nt * 8 + 2 * t;
            if (OUT_TF32) {
                uint32_t* C = (uint32_t*)Cv;
                *(uint2*)(C + (size_t)r_lo * N + cc) =
                    make_uint2(cvt_tf32(acc[mt][nt][0]), cvt_tf32(acc[mt][nt][1]));
                *(uint2*)(C + (size_t)(r_lo + 8) * N + cc) =
                    make_uint2(cvt_tf32(acc[mt][nt][2]), cvt_tf32(acc[mt][nt][3]));
            } else {
                float* C = (float*)Cv;
                *(float2*)(C + (size_t)r_lo * N + cc) =
                    make_float2(acc[mt][nt][0], acc[mt][nt][1]);
                *(float2*)(C + (size_t)(r_lo + 8) * N + cc) =
                    make_float2(acc[mt][nt][2], acc[mt][nt][3]);
            }
        }
    }
}

// ---------------------------------------------------------------------------
// Causal flash attention, tf32 mma.sync. EXACT Round-13 structure (BQ=128,
// 256 threads, 2 CTAs/SM via reg cap, 2-stage cp.async, ldmatrix K/Q/P,
// V stride 68). Single retained micro-opt vs Round-13: Q pre-scaled by
// 0.125 at staging (power-of-two -> bit-exact; removes 32 FMUL/tile/warp).
// ---------------------------------------------------------------------------
#define ATT_SROW 68
#define ATT_VS   (64 * ATT_SROW)
#define ATT_STG  (2 * 64 * ATT_SROW)
#define ATT_PS   (2 * ATT_STG)
#define ATT_SMEM_BYTES ((ATT_PS + 128 * ATT_SROW) * 4)   // 104448

__global__ __launch_bounds__(256, 2)
void attn_mma(const uint32_t* __restrict__ qkv, uint32_t* __restrict__ out) {
    extern __shared__ __align__(16) uint32_t sm2[];
    const uint32_t s2base = smem_u32(sm2);

    const int bh = blockIdx.y;
    const int b  = bh >> 4;
    const int h  = bh & 15;
    const int q0 = (int)(gridDim.x - 1 - blockIdx.x) << 7;

    const int tid  = threadIdx.x;
    const int wid  = tid >> 5;
    const int lane = tid & 31;
    const int g    = lane >> 2;
    const int t    = lane & 3;
    const int j8   = lane >> 3;
    const int r8   = lane & 7;

    const size_t row_base = (size_t)b * S_LEN;

    const int lr  = tid >> 2;
    const int lcb = (tid & 3) * 16;
    const uint32_t kdst0 = s2base + (uint32_t)(lr * ATT_SROW + lcb) * 4;
    const uint32_t vdst0 = kdst0 + (uint32_t)(ATT_VS * 4);
    const uint32_t* kgbase = qkv + (row_base + lr) * QKV_LD + D_DIM + h * HD_ + lcb;

    const uint32_t kldm = s2base +
        (uint32_t)(((j8 >> 1) * 8 + r8) * ATT_SROW + (j8 & 1) * 4) * 4;
    const uint32_t pldm = s2base +
        (uint32_t)(ATT_PS + (wid * 16 + (j8 & 1) * 8 + r8) * ATT_SROW + (j8 >> 1) * 4) * 4;

    const int nkt = (q0 >> 6) + 2;

    {
#pragma unroll
        for (int i = 0; i < 4; i++) {
            CP_ASYNC16(kdst0 + i * 16, kgbase + i * 4);
            CP_ASYNC16(vdst0 + i * 16, kgbase + D_DIM + i * 4);
        }
        CP_COMMIT();
    }

    // ---- stage Q tile, pre-scaled by 0.125 (exact: exponent-only) ----
#pragma unroll
    for (int i = 0; i < 8; i++) {
        const int idx = tid + i * 256;
        const int r   = idx >> 4;
        const int c4  = (idx & 15) * 4;
        uint4 v = *(const uint4*)(qkv + (row_base + q0 + r) * QKV_LD + h * HD_ + c4);
        uint32_t* p = sm2 + ATT_PS + r * ATT_SROW + c4;
        p[0] = __float_as_uint(__uint_as_float(v.x) * 0.125f);
        p[1] = __float_as_uint(__uint_as_float(v.y) * 0.125f);
        p[2] = __float_as_uint(__uint_as_float(v.z) * 0.125f);
        p[3] = __float_as_uint(__uint_as_float(v.w) * 0.125f);
    }
    __syncthreads();

    uint32_t qf[8][4];
#pragma unroll
    for (int ks = 0; ks < 8; ks++)
        LDSM_X4(qf[ks][0], qf[ks][1], qf[ks][2], qf[ks][3],
                pldm + (uint32_t)(ks * 8) * 4);

    float m0 = -1e30f, m1 = -1e30f, l0 = 0.f, l1 = 0.f;
    float o[8][4];
#pragma unroll
    for (int nt = 0; nt < 8; nt++)
#pragma unroll
        for (int j = 0; j < 4; j++) o[nt][j] = 0.f;

    uint32_t* const pw = sm2 + ATT_PS + wid * (16 * ATT_SROW);
    const int myrowmax = q0 + wid * 16 + 15;
    const unsigned FULL = 0xffffffffu;

    for (int kt = 0; kt < nkt; kt++) {
        const int k0 = kt << 6;

        CP_WAIT(0);
        __syncthreads();

        if (kt + 1 < nkt) {
            const uint32_t so = (uint32_t)(((kt + 1) & 1) * ATT_STG) * 4;
            const uint32_t* kg = kgbase + (size_t)((kt + 1) << 6) * QKV_LD;
#pragma unroll
            for (int i = 0; i < 4; i++) {
                CP_ASYNC16(kdst0 + so + i * 16, kg + i * 4);
                CP_ASYNC16(vdst0 + so + i * 16, kg + D_DIM + i * 4);
            }
            CP_COMMIT();
        }

        const uint32_t kso = (uint32_t)((kt & 1) * ATT_STG) * 4;
        const uint32_t* Vsb = sm2 + (size_t)(kt & 1) * ATT_STG + ATT_VS;

        if (k0 <= myrowmax) {
            float acc[8][4];
#pragma unroll
            for (int nt = 0; nt < 8; nt++)
#pragma unroll
                for (int j = 0; j < 4; j++) acc[nt][j] = 0.f;

#pragma unroll
            for (int ks = 0; ks < 8; ks++) {
                uint32_t bf[8][2];
#pragma unroll
                for (int p = 0; p < 4; p++)
                    LDSM_X4(bf[2 * p][0], bf[2 * p][1], bf[2 * p + 1][0], bf[2 * p + 1][1],
                            kldm + kso + (uint32_t)(p * 16 * ATT_SROW + ks * 8) * 4);
#pragma unroll
                for (int nt = 0; nt < 8; nt++)
                    MMA_TF32(acc[nt][0], acc[nt][1], acc[nt][2], acc[nt][3],
                             qf[ks][0], qf[ks][1], qf[ks][2], qf[ks][3],
                             bf[nt][0], bf[nt][1]);
            }

            // ---- causal mask (scores already scaled via Q) ----
            const int r0 = q0 + wid * 16 + g;
            const int r1 = r0 + 8;
            if (k0 + 63 > q0 + wid * 16) {
#pragma unroll
                for (int nt = 0; nt < 8; nt++) {
                    const int col = k0 + nt * 8 + 2 * t;
                    if (col > r0)     acc[nt][0] = -1e30f;
                    if (col + 1 > r0) acc[nt][1] = -1e30f;
                    if (col > r1)     acc[nt][2] = -1e30f;
                    if (col + 1 > r1) acc[nt][3] = -1e30f;
                }
            }

            float mt0 = -1e30f, mt1 = -1e30f;
#pragma unroll
            for (int nt = 0; nt < 8; nt++) {
                mt0 = fmaxf(mt0, fmaxf(acc[nt][0], acc[nt][1]));
                mt1 = fmaxf(mt1, fmaxf(acc[nt][2], acc[nt][3]));
            }
            mt0 = fmaxf(mt0, __shfl_xor_sync(FULL, mt0, 1));
            mt0 = fmaxf(mt0, __shfl_xor_sync(FULL, mt0, 2));
            mt1 = fmaxf(mt1, __shfl_xor_sync(FULL, mt1, 1));
            mt1 = fmaxf(mt1, __shfl_xor_sync(FULL, mt1, 2));

            const float mn0 = fmaxf(m0, mt0);
            const float mn1 = fmaxf(m1, mt1);
            const float c0 = __expf(m0 - mn0);
            const float c1 = __expf(m1 - mn1);
            float s0 = 0.f, s1 = 0.f;
#pragma unroll
            for (int nt = 0; nt < 8; nt++) {
                acc[nt][0] = __expf(acc[nt][0] - mn0); s0 += acc[nt][0];
                acc[nt][1] = __expf(acc[nt][1] - mn0); s0 += acc[nt][1];
                acc[nt][2] = __expf(acc[nt][2] - mn1); s1 += acc[nt][2];
                acc[nt][3] = __expf(acc[nt][3] - mn1); s1 += acc[nt][3];
            }
            s0 += __shfl_xor_sync(FULL, s0, 1);
            s0 += __shfl_xor_sync(FULL, s0, 2);
            s1 += __shfl_xor_sync(FULL, s1, 1);
            s1 += __shfl_xor_sync(FULL, s1, 2);
            l0 = l0 * c0 + s0; m0 = mn0;
            l1 = l1 * c1 + s1; m1 = mn1;
#pragma unroll
            for (int nt = 0; nt < 8; nt++) {
                o[nt][0] *= c0; o[nt][1] *= c0;
                o[nt][2] *= c1; o[nt][3] *= c1;
            }

#pragma unroll
            for (int nt = 0; nt < 8; nt++) {
                uint32_t* p0 = pw + g * ATT_SROW + nt * 8 + 2 * t;
                uint32_t* p1 = pw + (g + 8) * ATT_SROW + nt * 8 + 2 * t;
                p0[0] = cvt_tf32(acc[nt][0]); p0[1] = cvt_tf32(acc[nt][1]);
                p1[0] = cvt_tf32(acc[nt][2]); p1[1] = cvt_tf32(acc[nt][3]);
            }
            __syncwarp();

#pragma unroll
            for (int ks = 0; ks < 8; ks++) {
                uint32_t pa[4];
                LDSM_X4(pa[0], pa[1], pa[2], pa[3], pldm + (uint32_t)(ks * 8) * 4);
#pragma unroll
                for (int nt = 0; nt < 8; nt++) {
                    const uint32_t* vb = Vsb + (ks * 8 + t) * ATT_SROW + nt * 8 + g;
                    const uint32_t b0 = vb[0];
                    const uint32_t b1 = vb[4 * ATT_SROW];
                    MMA_TF32(o[nt][0], o[nt][1], o[nt][2], o[nt][3],
                             pa[0], pa[1], pa[2], pa[3], b0, b1);
                }
            }
        }
    }

    const float i0 = 1.0f / l0;
    const float i1 = 1.0f / l1;
    const size_t r0 = row_base + q0 + wid * 16 + g;
#pragma unroll
    for (int nt = 0; nt < 8; nt++) {
        const int col = h * HD_ + nt * 8 + 2 * t;
        *(uint2*)(out + r0 * D_DIM + col) =
            make_uint2(cvt_tf32(o[nt][0] * i0), cvt_tf32(o[nt][1] * i0));
        *(uint2*)(out + (r0 + 8) * D_DIM + col) =
            make_uint2(cvt_tf32(o[nt][2] * i1), cvt_tf32(o[nt][3] * i1));
    }
}

// ---------------------------------------------------------------------------
extern "C" void kernel_launch(void* const* d_in, const int* in_sizes, int n_in,
                              void* d_out, int out_size) {
    const float* x      = (const float*)d_in[0];  // [B, S, D]
    const float* w_attn = (const float*)d_in[1];  // [3D, D]
    const float* w_proj = (const float*)d_in[2];  // [D, D]
    float* outp         = (float*)d_out;          // [B, S, D]

    void *p_xa, *p_wa, *p_wp, *p_qkv, *p_att;
    cudaGetSymbolAddress(&p_xa, g_xa);
    cudaGetSymbolAddress(&p_wa, g_wa);
    cudaGetSymbolAddress(&p_wp, g_wp);
    cudaGetSymbolAddress(&p_qkv, g_qkv);
    cudaGetSymbolAddress(&p_att, g_att);

    const int M = B_SZ * S_LEN;  // 8192

    cudaFuncSetAttribute(sgemm_tc<true>,
                         cudaFuncAttributeMaxDynamicSharedMemorySize, GSMEM_BYTES);
    cudaFuncSetAttribute(sgemm_tc<false>,
                         cudaFuncAttributeMaxDynamicSharedMemorySize, GSMEM_BYTES);
    cudaFuncSetAttribute(attn_mma,
                         cudaFuncAttributeMaxDynamicSharedMemorySize, ATT_SMEM_BYTES);

    // 0) one-shot tf32 conversion of inputs
    cvt_inputs<<<NCVT4 / 256, 256>>>((const float4*)x, (const float4*)w_attn,
                                     (const float4*)w_proj);

    // 1) QKV = X @ W_attn^T  -> tf32 bits   (128x128 tiles, 2 CTAs/SM)
    sgemm_tc<true><<<dim3(QKV_LD / 128, M / 128), 256, GSMEM_BYTES>>>(
        (const uint32_t*)p_xa, (const uint32_t*)p_wa, p_qkv, M, QKV_LD, D_DIM);

    // 2) causal attention -> att (tf32 bits)  (BQ=128, 2 CTAs/SM)
    attn_mma<<<dim3(S_LEN / 128, B_SZ * NH), 256, ATT_SMEM_BYTES>>>(
        (const uint32_t*)p_qkv, (uint32_t*)p_att);

    // 3) out = att @ W_proj^T  -> fp32      (128x128 tiles, 2 CTAs/SM)
    sgemm_tc<false><<<dim3(D_DIM / 128, M / 128), 256, GSMEM_BYTES>>>(
        (const uint32_t*)p_att, (const uint32_t*)p_wp, outp, M, D_DIM, D_DIM);
}

// round 17
// speedup vs baseline: 1.5325x; 1.0912x over previous
#include <cuda_runtime.h>
#include <math.h>
#include <cstdint>

#define B_SZ   4
#define S_LEN  2048
#define D_DIM  1024
#define NH     16
#define HD_    64
#define QKV_LD 3072

// Scratch (no runtime allocation allowed). All tf32-bit buffers are uint32.
__device__ uint32_t g_xa[(size_t)B_SZ * S_LEN * D_DIM];   // x  (tf32)
__device__ uint32_t g_wa[(size_t)QKV_LD * D_DIM];         // w_attn (tf32)
__device__ uint32_t g_wp[(size_t)D_DIM * D_DIM];          // w_proj (tf32)
__device__ uint32_t g_qkv[(size_t)B_SZ * S_LEN * QKV_LD]; // qkv (tf32)
__device__ uint32_t g_att[(size_t)B_SZ * S_LEN * D_DIM];  // attn out (tf32)

// ---------------------------------------------------------------------------
// helpers (target-neutral; plain sm_103)
// ---------------------------------------------------------------------------
__device__ __forceinline__ uint32_t cvt_tf32(float f) {
    uint32_t r;
    asm("cvt.rna.tf32.f32 %0, %1;" : "=r"(r) : "f"(f));
    return r;
}

__device__ __forceinline__ uint32_t smem_u32(const void* p) {
    uint32_t a;
    asm("{ .reg .u64 t; cvta.to.shared.u64 t, %1; cvt.u32.u64 %0, t; }"
        : "=r"(a) : "l"(p));
    return a;
}

#define CP_ASYNC16(dst_u32, src_ptr)                                          \
    asm volatile("cp.async.cg.shared.global [%0], [%1], 16;"                  \
                 :: "r"(dst_u32), "l"(src_ptr))
#define CP_COMMIT() asm volatile("cp.async.commit_group;" ::: "memory")
#define CP_WAIT(n)  asm volatile("cp.async.wait_group %0;" :: "n"(n) : "memory")

#define MMA_TF32(d0, d1, d2, d3, a0, a1, a2, a3, b0, b1)                      \
    asm volatile(                                                             \
        "mma.sync.aligned.m16n8k8.row.col.f32.tf32.tf32.f32 "                 \
        "{%0,%1,%2,%3}, {%4,%5,%6,%7}, {%8,%9}, {%0,%1,%2,%3};"               \
        : "+f"(d0), "+f"(d1), "+f"(d2), "+f"(d3)                              \
        : "r"(a0), "r"(a1), "r"(a2), "r"(a3), "r"(b0), "r"(b1))

// ldmatrix x4: lanes 0-7 supply row addresses of matrix 0, 8-15 matrix 1, etc.
#define LDSM_X4(r0, r1, r2, r3, addr)                                         \
    asm volatile("ldmatrix.sync.aligned.m8n8.x4.shared.b16 {%0,%1,%2,%3}, [%4];" \
                 : "=r"(r0), "=r"(r1), "=r"(r2), "=r"(r3) : "r"(addr))

// ---------------------------------------------------------------------------
// One-shot tf32 conversion of x, w_attn, w_proj (bandwidth-bound, ~13us).
// ---------------------------------------------------------------------------
#define NX4  (B_SZ * S_LEN * D_DIM / 4)
#define NWA4 (QKV_LD * D_DIM / 4)
#define NWP4 (D_DIM * D_DIM / 4)
#define NCVT4 (NX4 + NWA4 + NWP4)

__global__ __launch_bounds__(256)
void cvt_inputs(const float4* __restrict__ x, const float4* __restrict__ wa,
                const float4* __restrict__ wp) {
    const int i = blockIdx.x * 256 + threadIdx.x;
    float4 v;
    uint4* dst;
    if (i < NX4)            { v = x[i];               dst = (uint4*)g_xa + i; }
    else if (i < NX4 + NWA4){ v = wa[i - NX4];        dst = (uint4*)g_wa + (i - NX4); }
    else                    { v = wp[i - NX4 - NWA4]; dst = (uint4*)g_wp + (i - NX4 - NWA4); }
    uint4 o;
    o.x = cvt_tf32(v.x); o.y = cvt_tf32(v.y);
    o.z = cvt_tf32(v.z); o.w = cvt_tf32(v.w);
    *dst = o;
}

// ---------------------------------------------------------------------------
// Tensor-core GEMM (tf32 mma.sync, NT): C[M,N] = A[M,K] * B[N,K]^T.
// (Round-10 version, unchanged: 2 CTAs/SM, 128x128 tile, 3-stage cp.async,
// ldmatrix fragments.)
// ---------------------------------------------------------------------------
#define SROW 36
#define ASTG (128 * SROW)
#define STG_BYTES (2 * ASTG * 4)               // A+B per stage = 36864
#define GSMEM_BYTES (3 * STG_BYTES)            // 110592

template <bool OUT_TF32>
__global__ __launch_bounds__(256, 2)
void sgemm_tc(const uint32_t* __restrict__ A, const uint32_t* __restrict__ B,
              void* __restrict__ Cv, int M, int N, int K) {
    extern __shared__ __align__(16) uint32_t sm[];
    const uint32_t sbase = smem_u32(sm);

    const int tid  = threadIdx.x;
    const int wid  = tid >> 5;
    const int lane = tid & 31;
    const int g    = lane >> 2;
    const int t    = lane & 3;
    const int j8   = lane >> 3;
    const int r8   = lane & 7;
    const int row0 = blockIdx.y << 7;
    const int col0 = blockIdx.x << 7;
    const int warp_m = (wid & 1) * 64;
    const int warp_n = (wid >> 1) * 32;

    const int rbase = tid >> 3;
    const int c4    = (tid & 7) * 4;

    const uint32_t* Abase = A + (size_t)(row0 + rbase) * K + c4;
    const uint32_t* Bbase = B + (size_t)(col0 + rbase) * K + c4;
    const uint32_t adst = sbase + (uint32_t)(rbase * SROW + c4) * 4;
    const uint32_t bdst = sbase + (uint32_t)(ASTG + rbase * SROW + c4) * 4;

    const uint32_t aldm = sbase +
        (uint32_t)((warp_m + (j8 & 1) * 8 + r8) * SROW + (j8 >> 1) * 4) * 4;
    const uint32_t bldm = sbase +
        (uint32_t)(ASTG + (warp_n + (j8 >> 1) * 8 + r8) * SROW + (j8 & 1) * 4) * 4;

    const int KT = K >> 5;

    float acc[4][4][4];
#pragma unroll
    for (int i = 0; i < 4; i++)
#pragma unroll
        for (int j = 0; j < 4; j++)
#pragma unroll
            for (int k = 0; k < 4; k++) acc[i][j][k] = 0.f;

#pragma unroll
    for (int s = 0; s < 2; s++) {
        const int kb = s << 5;
        const uint32_t so = (uint32_t)s * STG_BYTES;
#pragma unroll
        for (int i = 0; i < 4; i++) {
            CP_ASYNC16(adst + so + i * (32 * SROW * 4), Abase + (size_t)(32 * i) * K + kb);
            CP_ASYNC16(bdst + so + i * (32 * SROW * 4), Bbase + (size_t)(32 * i) * K + kb);
        }
        CP_COMMIT();
    }

    uint32_t so = 0;
    int so_next = STG_BYTES;

    for (int kt = 0; kt < KT; kt++) {
        CP_WAIT(1);
        __syncthreads();

        if (kt + 2 < KT) {
            const int kb = (kt + 2) << 5;
            const uint32_t po = (uint32_t)(((kt + 2) % 3)) * STG_BYTES;
#pragma unroll
            for (int i = 0; i < 4; i++) {
                CP_ASYNC16(adst + po + i * (32 * SROW * 4), Abase + (size_t)(32 * i) * K + kb);
                CP_ASYNC16(bdst + po + i * (32 * SROW * 4), Bbase + (size_t)(32 * i) * K + kb);
            }
        }
        CP_COMMIT();

#pragma unroll
        for (int ks = 0; ks < 4; ks++) {
            uint32_t af[4][4], bf[4][2];
#pragma unroll
            for (int mt = 0; mt < 4; mt++)
                LDSM_X4(af[mt][0], af[mt][1], af[mt][2], af[mt][3],
                        aldm + so + (uint32_t)(mt * 16 * SROW + ks * 8) * 4);
#pragma unroll
            for (int p = 0; p < 2; p++)
                LDSM_X4(bf[2 * p][0], bf[2 * p][1], bf[2 * p + 1][0], bf[2 * p + 1][1],
                        bldm + so + (uint32_t)(p * 16 * SROW + ks * 8) * 4);
#pragma unroll
            for (int mt = 0; mt < 4; mt++)
#pragma unroll
                for (int nt = 0; nt < 4; nt++)
                    MMA_TF32(acc[mt][nt][0], acc[mt][nt][1],
                             acc[mt][nt][2], acc[mt][nt][3],
                             af[mt][0], af[mt][1], af[mt][2], af[mt][3],
                             bf[nt][0], bf[nt][1]);
        }

        so = (uint32_t)so_next;
        so_next += STG_BYTES;
        if (so_next == 3 * STG_BYTES) so_next = 0;
    }

#pragma unroll
    for (int mt = 0; mt < 4; mt++) {
        const int r_lo = row0 + warp_m + mt * 16 + g;
#pragma unroll
        for (int nt = 0; nt < 4; nt++) {
            const int cc = col0 + warp_n + nt * 8 + 2 * t;
            if (OUT_TF32) {
                uint32_t* C = (uint32_t*)Cv;
                *(uint2*)(C + (size_t)r_lo * N + cc) =
                    make_uint2(cvt_tf32(acc[mt][nt][0]), cvt_tf32(acc[mt][nt][1]));
                *(uint2*)(C + (size_t)(r_lo + 8) * N + cc) =
                    make_uint2(cvt_tf32(acc[mt][nt][2]), cvt_tf32(acc[mt][nt][3]));
            } else {
                float* C = (float*)Cv;
                *(float2*)(C + (size_t)r_lo * N + cc) =
                    make_float2(acc[mt][nt][0], acc[mt][nt][1]);
                *(float2*)(C + (size_t)(r_lo + 8) * N + cc) =
                    make_float2(acc[mt][nt][2], acc[mt][nt][3]);
            }
        }
    }
}

// ---------------------------------------------------------------------------
// Causal flash attention, tf32 mma.sync. Round-16 structure (BQ=128,
// 256 threads, 2 CTAs/SM, 2-stage cp.async, ldmatrix K/Q/P, Q pre-scaled).
// Round-17 single change: V row stride 68 -> 72. PV scalar-LDS bank index
// becomes (8t+g)%32 — a bijection over the warp -> conflict-free (stride 68
// gave (4t+g)%32 with systematic 2-way conflicts). Layout-only; bit-exact.
// Smem: 2 stages x (K 64x68 | V 64x72) + Q/P 128x68 = 106496 B; 2 CTAs/SM.
// ---------------------------------------------------------------------------
#define ATT_SROW 68
#define ATT_VROW 72
#define ATT_KSZ  (64 * ATT_SROW)                  // 4352 u32
#define ATT_STG  (ATT_KSZ + 64 * ATT_VROW)        // 8960 u32 per stage
#define ATT_PS   (2 * ATT_STG)                    // 17920 u32
#define ATT_SMEM_BYTES ((ATT_PS + 128 * ATT_SROW) * 4)   // 106496

__global__ __launch_bounds__(256, 2)
void attn_mma(const uint32_t* __restrict__ qkv, uint32_t* __restrict__ out) {
    extern __shared__ __align__(16) uint32_t sm2[];
    const uint32_t s2base = smem_u32(sm2);

    const int bh = blockIdx.y;
    const int b  = bh >> 4;
    const int h  = bh & 15;
    const int q0 = (int)(gridDim.x - 1 - blockIdx.x) << 7;

    const int tid  = threadIdx.x;
    const int wid  = tid >> 5;
    const int lane = tid & 31;
    const int g    = lane >> 2;
    const int t    = lane & 3;
    const int j8   = lane >> 3;
    const int r8   = lane & 7;

    const size_t row_base = (size_t)b * S_LEN;

    const int lr  = tid >> 2;
    const int lcb = (tid & 3) * 16;
    const uint32_t kdst0 = s2base + (uint32_t)(lr * ATT_SROW + lcb) * 4;
    const uint32_t vdst0 = s2base + (uint32_t)(ATT_KSZ + lr * ATT_VROW + lcb) * 4;
    const uint32_t* kgbase = qkv + (row_base + lr) * QKV_LD + D_DIM + h * HD_ + lcb;

    const uint32_t kldm = s2base +
        (uint32_t)(((j8 >> 1) * 8 + r8) * ATT_SROW + (j8 & 1) * 4) * 4;
    const uint32_t pldm = s2base +
        (uint32_t)(ATT_PS + (wid * 16 + (j8 & 1) * 8 + r8) * ATT_SROW + (j8 >> 1) * 4) * 4;

    const int nkt = (q0 >> 6) + 2;

    {
#pragma unroll
        for (int i = 0; i < 4; i++) {
            CP_ASYNC16(kdst0 + i * 16, kgbase + i * 4);
            CP_ASYNC16(vdst0 + i * 16, kgbase + D_DIM + i * 4);
        }
        CP_COMMIT();
    }

    // ---- stage Q tile, pre-scaled by 0.125 (exact: exponent-only) ----
#pragma unroll
    for (int i = 0; i < 8; i++) {
        const int idx = tid + i * 256;
        const int r   = idx >> 4;
        const int c4  = (idx & 15) * 4;
        uint4 v = *(const uint4*)(qkv + (row_base + q0 + r) * QKV_LD + h * HD_ + c4);
        uint32_t* p = sm2 + ATT_PS + r * ATT_SROW + c4;
        p[0] = __float_as_uint(__uint_as_float(v.x) * 0.125f);
        p[1] = __float_as_uint(__uint_as_float(v.y) * 0.125f);
        p[2] = __float_as_uint(__uint_as_float(v.z) * 0.125f);
        p[3] = __float_as_uint(__uint_as_float(v.w) * 0.125f);
    }
    __syncthreads();

    uint32_t qf[8][4];
#pragma unroll
    for (int ks = 0; ks < 8; ks++)
        LDSM_X4(qf[ks][0], qf[ks][1], qf[ks][2], qf[ks][3],
                pldm + (uint32_t)(ks * 8) * 4);

    float m0 = -1e30f, m1 = -1e30f, l0 = 0.f, l1 = 0.f;
    float o[8][4];
#pragma unroll
    for (int nt = 0; nt < 8; nt++)
#pragma unroll
        for (int j = 0; j < 4; j++) o[nt][j] = 0.f;

    uint32_t* const pw = sm2 + ATT_PS + wid * (16 * ATT_SROW);
    const int myrowmax = q0 + wid * 16 + 15;
    const unsigned FULL = 0xffffffffu;

    for (int kt = 0; kt < nkt; kt++) {
        const int k0 = kt << 6;

        CP_WAIT(0);
        __syncthreads();

        if (kt + 1 < nkt) {
            const uint32_t so = (uint32_t)(((kt + 1) & 1) * ATT_STG) * 4;
            const uint32_t* kg = kgbase + (size_t)((kt + 1) << 6) * QKV_LD;
#pragma unroll
            for (int i = 0; i < 4; i++) {
                CP_ASYNC16(kdst0 + so + i * 16, kg + i * 4);
                CP_ASYNC16(vdst0 + so + i * 16, kg + D_DIM + i * 4);
            }
            CP_COMMIT();
        }

        const uint32_t kso = (uint32_t)((kt & 1) * ATT_STG) * 4;
        const uint32_t* Vsb = sm2 + (size_t)(kt & 1) * ATT_STG + ATT_KSZ;

        if (k0 <= myrowmax) {
            float acc[8][4];
#pragma unroll
            for (int nt = 0; nt < 8; nt++)
#pragma unroll
                for (int j = 0; j < 4; j++) acc[nt][j] = 0.f;

#pragma unroll
            for (int ks = 0; ks < 8; ks++) {
                uint32_t bf[8][2];
#pragma unroll
                for (int p = 0; p < 4; p++)
                    LDSM_X4(bf[2 * p][0], bf[2 * p][1], bf[2 * p + 1][0], bf[2 * p + 1][1],
                            kldm + kso + (uint32_t)(p * 16 * ATT_SROW + ks * 8) * 4);
#pragma unroll
                for (int nt = 0; nt < 8; nt++)
                    MMA_TF32(acc[nt][0], acc[nt][1], acc[nt][2], acc[nt][3],
                             qf[ks][0], qf[ks][1], qf[ks][2], qf[ks][3],
                             bf[nt][0], bf[nt][1]);
            }

            // ---- causal mask (scores already scaled via Q) ----
            const int r0 = q0 + wid * 16 + g;
            const int r1 = r0 + 8;
            if (k0 + 63 > q0 + wid * 16) {
#pragma unroll
                for (int nt = 0; nt < 8; nt++) {
                    const int col = k0 + nt * 8 + 2 * t;
                    if (col > r0)     acc[nt][0] = -1e30f;
                    if (col + 1 > r0) acc[nt][1] = -1e30f;
                    if (col > r1)     acc[nt][2] = -1e30f;
                    if (col + 1 > r1) acc[nt][3] = -1e30f;
                }
            }

            float mt0 = -1e30f, mt1 = -1e30f;
#pragma unroll
            for (int nt = 0; nt < 8; nt++) {
                mt0 = fmaxf(mt0, fmaxf(acc[nt][0], acc[nt][1]));
                mt1 = fmaxf(mt1, fmaxf(acc[nt][2], acc[nt][3]));
            }
            mt0 = fmaxf(mt0, __shfl_xor_sync(FULL, mt0, 1));
            mt0 = fmaxf(mt0, __shfl_xor_sync(FULL, mt0, 2));
            mt1 = fmaxf(mt1, __shfl_xor_sync(FULL, mt1, 1));
            mt1 = fmaxf(mt1, __shfl_xor_sync(FULL, mt1, 2));

            const float mn0 = fmaxf(m0, mt0);
            const float mn1 = fmaxf(m1, mt1);
            const float c0 = __expf(m0 - mn0);
            const float c1 = __expf(m1 - mn1);
            float s0 = 0.f, s1 = 0.f;
#pragma unroll
            for (int nt = 0; nt < 8; nt++) {
                acc[nt][0] = __expf(acc[nt][0] - mn0); s0 += acc[nt][0];
                acc[nt][1] = __expf(acc[nt][1] - mn0); s0 += acc[nt][1];
                acc[nt][2] = __expf(acc[nt][2] - mn1); s1 += acc[nt][2];
                acc[nt][3] = __expf(acc[nt][3] - mn1); s1 += acc[nt][3];
            }
            s0 += __shfl_xor_sync(FULL, s0, 1);
            s0 += __shfl_xor_sync(FULL, s0, 2);
            s1 += __shfl_xor_sync(FULL, s1, 1);
            s1 += __shfl_xor_sync(FULL, s1, 2);
            l0 = l0 * c0 + s0; m0 = mn0;
            l1 = l1 * c1 + s1; m1 = mn1;
#pragma unroll
            for (int nt = 0; nt < 8; nt++) {
                o[nt][0] *= c0; o[nt][1] *= c0;
                o[nt][2] *= c1; o[nt][3] *= c1;
            }

#pragma unroll
            for (int nt = 0; nt < 8; nt++) {
                uint32_t* p0 = pw + g * ATT_SROW + nt * 8 + 2 * t;
                uint32_t* p1 = pw + (g + 8) * ATT_SROW + nt * 8 + 2 * t;
                p0[0] = cvt_tf32(acc[nt][0]); p0[1] = cvt_tf32(acc[nt][1]);
                p1[0] = cvt_tf32(acc[nt][2]); p1[1] = cvt_tf32(acc[nt][3]);
            }
            __syncwarp();

#pragma unroll
            for (int ks = 0; ks < 8; ks++) {
                uint32_t pa[4];
                LDSM_X4(pa[0], pa[1], pa[2], pa[3], pldm + (uint32_t)(ks * 8) * 4);
#pragma unroll
                for (int nt = 0; nt < 8; nt++) {
                    const uint32_t* vb = Vsb + (ks * 8 + t) * ATT_VROW + nt * 8 + g;
                    const uint32_t b0 = vb[0];
                    const uint32_t b1 = vb[4 * ATT_VROW];
                    MMA_TF32(o[nt][0], o[nt][1], o[nt][2], o[nt][3],
                             pa[0], pa[1], pa[2], pa[3], b0, b1);
                }
            }
        }
    }

    const float i0 = 1.0f / l0;
    const float i1 = 1.0f / l1;
    const size_t r0 = row_base + q0 + wid * 16 + g;
#pragma unroll
    for (int nt = 0; nt < 8; nt++) {
        const int col = h * HD_ + nt * 8 + 2 * t;
        *(uint2*)(out + r0 * D_DIM + col) =
            make_uint2(cvt_tf32(o[nt][0] * i0), cvt_tf32(o[nt][1] * i0));
        *(uint2*)(out + (r0 + 8) * D_DIM + col) =
            make_uint2(cvt_tf32(o[nt][2] * i1), cvt_tf32(o[nt][3] * i1));
    }
}

// ---------------------------------------------------------------------------
extern "C" void kernel_launch(void* const* d_in, const int* in_sizes, int n_in,
                              void* d_out, int out_size) {
    const float* x      = (const float*)d_in[0];  // [B, S, D]
    const float* w_attn = (const float*)d_in[1];  // [3D, D]
    const float* w_proj = (const float*)d_in[2];  // [D, D]
    float* outp         = (float*)d_out;          // [B, S, D]

    void *p_xa, *p_wa, *p_wp, *p_qkv, *p_att;
    cudaGetSymbolAddress(&p_xa, g_xa);
    cudaGetSymbolAddress(&p_wa, g_wa);
    cudaGetSymbolAddress(&p_wp, g_wp);
    cudaGetSymbolAddress(&p_qkv, g_qkv);
    cudaGetSymbolAddress(&p_att, g_att);

    const int M = B_SZ * S_LEN;  // 8192

    cudaFuncSetAttribute(sgemm_tc<true>,
                         cudaFuncAttributeMaxDynamicSharedMemorySize, GSMEM_BYTES);
    cudaFuncSetAttribute(sgemm_tc<false>,
                         cudaFuncAttributeMaxDynamicSharedMemorySize, GSMEM_BYTES);
    cudaFuncSetAttribute(attn_mma,
                         cudaFuncAttributeMaxDynamicSharedMemorySize, ATT_SMEM_BYTES);

    // 0) one-shot tf32 conversion of inputs
    cvt_inputs<<<NCVT4 / 256, 256>>>((const float4*)x, (const float4*)w_attn,
                                     (const float4*)w_proj);

    // 1) QKV = X @ W_attn^T  -> tf32 bits   (128x128 tiles, 2 CTAs/SM)
    sgemm_tc<true><<<dim3(QKV_LD / 128, M / 128), 256, GSMEM_BYTES>>>(
        (const uint32_t*)p_xa, (const uint32_t*)p_wa, p_qkv, M, QKV_LD, D_DIM);

    // 2) causal attention -> att (tf32 bits)  (BQ=128, 2 CTAs/SM)
    attn_mma<<<dim3(S_LEN / 128, B_SZ * NH), 256, ATT_SMEM_BYTES>>>(
        (const uint32_t*)p_qkv, (uint32_t*)p_att);

    // 3) out = att @ W_proj^T  -> fp32      (128x128 tiles, 2 CTAs/SM)
    sgemm_tc<false><<<dim3(D_DIM / 128, M / 128), 256, GSMEM_BYTES>>>(
        (const uint32_t*)p_att, (const uint32_t*)p_wp, outp, M, D_DIM, D_DIM);
}